// round 5
// baseline (speedup 1.0000x reference)
#include <cuda_runtime.h>
#include <cstdint>

// FlowNet correlation on GB300/B200 — R4: FFMA2 with zero-repack operands.
// out[b, dyi*21+dxi, h, w] = (1/256) * sum_c in1[b,c,h,w] * in2[b,c,h+dy,w+dx]
// dy = 2*(dyi-10), dx = 2*(dxi-10), zero padding.
// Shapes: B=8, C=256, H=96, W=128, G=21, D=441.
//
//  - Parity-packed smem rows -> contiguous 24-float key windows, LDS.128.
//  - CTA(32,11): one (b,h), 11 dy rows, all 128 w. Thread: 4 w x 21 dx.
//  - Window loaded as ulonglong2: each LDS.128 directly yields two 64-bit
//    even-aligned f32x2 operands -> fma.rn.f32x2 with NO repack movs
//    (R3's mistake: 36 movs/channel cancelled the FMA savings).

#define CB    8
#define CC_   256
#define HH    96
#define WW    128
#define GG    21
#define DD    441
#define CHK   8
#define NCHK  32
#define NROW  11
#define SW    84
#define NTHR  352

#define B_BUF_FLOATS 14784
#define A_BUF_FLOATS 1024
#define A_REGION_OFF (2 * B_BUF_FLOATS)
#define SMEM_FLOATS  (2 * B_BUF_FLOATS + 2 * A_BUF_FLOATS)
#define SMEM_BYTES   (SMEM_FLOATS * 4)           // 126464

__device__ __forceinline__ uint64_t pk2(float lo, float hi) {
    uint64_t r;
    asm("mov.b64 %0, {%1, %2};" : "=l"(r) : "f"(lo), "f"(hi));
    return r;
}
__device__ __forceinline__ void upk2(uint64_t v, float& lo, float& hi) {
    asm("mov.b64 {%0, %1}, %2;" : "=f"(lo), "=f"(hi) : "l"(v));
}
__device__ __forceinline__ void ffma2(uint64_t& c, uint64_t a, uint64_t b) {
    asm("fma.rn.f32x2 %0, %1, %2, %0;" : "+l"(c) : "l"(a), "l"(b));
}

__global__ __launch_bounds__(NTHR, 1)
void corr_kernel(const float* __restrict__ in1,
                 const float* __restrict__ in2,
                 float* __restrict__ out)
{
    extern __shared__ float sm[];

    const int tx = threadIdx.x;
    const int ty = threadIdx.y;
    const int tid = ty * 32 + tx;
    const int s  = blockIdx.x;                  // dy half
    const int h  = blockIdx.y;
    const int b  = blockIdx.z;

    // ---- zero parity-halo regions of both buffers ----
    for (int i = tid; i < 2 * CHK * NROW * 2 * 20; i += NTHR) {
        int hseg = i % 20;
        int rest = i / 20;
        int par  = rest & 1;  rest >>= 1;
        int row  = rest % NROW; rest /= NROW;
        int ci   = rest % CHK;
        int buf  = rest / CHK;
        int idx  = (hseg < 10) ? hseg : (64 + hseg);
        sm[buf * B_BUF_FLOATS + ((ci * NROW + row) * 2 + par) * SW + idx] = 0.0f;
    }
    __syncthreads();

    const int par    = tx >> 4;
    const int xi     = tx & 15;
    const int dy_idx = s * NROW + ty;
    const bool active = (dy_idx < GG);
    const int base_w = 8 * xi + par;

    // paired accumulators: accp[kk][p] covers dxi (2p,2p+1) for even kk,
    // (1+2p,2+2p) for odd kk. Scalar leftover: dxi=20 (kk even), dxi=0 (kk odd).
    uint64_t accp[4][10];
    float    accs[4];
#pragma unroll
    for (int kk = 0; kk < 4; ++kk) {
        accs[kk] = 0.0f;
#pragma unroll
        for (int p = 0; p < 10; ++p) accp[kk][p] = 0ull;
    }

    float4 rB[8];
    float4 rA = make_float4(0.f, 0.f, 0.f, 0.f);

    auto loadRegs = [&](int chunk) {
        const int c0 = chunk * CHK;
#pragma unroll
        for (int i = 0; i < 8; ++i) {
            const int t  = tid + NTHR * i;
            const int m  = t & 31;
            const int ci = (t >> 5) & 7;
            const int j  = t >> 8;
            const int r  = h + 2 * (s * NROW + j) - 20;
            if ((unsigned)r < (unsigned)HH) {
                rB[i] = *reinterpret_cast<const float4*>(
                    in2 + ((((long)b * CC_ + c0 + ci) * HH + r) * WW + 4 * m));
            } else {
                rB[i] = make_float4(0.f, 0.f, 0.f, 0.f);
            }
        }
        if (tid < 256) {
            const int m  = tid & 31;
            const int ci = tid >> 5;
            rA = *reinterpret_cast<const float4*>(
                in1 + ((((long)b * CC_ + c0 + ci) * HH + h) * WW + 4 * m));
        }
    };

    auto stsRegs = [&](int buf) {
        float* B = sm + buf * B_BUF_FLOATS;
#pragma unroll
        for (int i = 0; i < 8; ++i) {
            const int t  = tid + NTHR * i;
            const int m  = t & 31;
            const int ci = (t >> 5) & 7;
            const int j  = t >> 8;
            float* pe = B + ((ci * NROW + j) * 2 + 0) * SW + 2 * m + 10;
            float* po = B + ((ci * NROW + j) * 2 + 1) * SW + 2 * m + 10;
            *reinterpret_cast<float2*>(pe) = make_float2(rB[i].x, rB[i].z);
            *reinterpret_cast<float2*>(po) = make_float2(rB[i].y, rB[i].w);
        }
        if (tid < 256) {
            const int m  = tid & 31;
            const int ci = tid >> 5;
            float* A = sm + A_REGION_OFF + buf * A_BUF_FLOATS;
            float* pe = A + (ci * 2 + 0) * 64 + 2 * m;
            float* po = A + (ci * 2 + 1) * 64 + 2 * m;
            *reinterpret_cast<float2*>(pe) = make_float2(rA.x, rA.z);
            *reinterpret_cast<float2*>(po) = make_float2(rA.y, rA.w);
        }
    };

    auto computeBuf = [&](int buf) {
        const float* Bb = sm + buf * B_BUF_FLOATS;
        const float* Ab = sm + A_REGION_OFF + buf * A_BUF_FLOATS;
#pragma unroll
        for (int ci = 0; ci < CHK; ++ci) {
            const float4 q4 = *reinterpret_cast<const float4*>(
                Ab + (ci * 2 + par) * 64 + 4 * xi);
            uint64_t qp[4];
            qp[0] = pk2(q4.x, q4.x);
            qp[1] = pk2(q4.y, q4.y);
            qp[2] = pk2(q4.z, q4.z);
            qp[3] = pk2(q4.w, q4.w);

            // 24-float window as 6 LDS.128, each yielding two 64-bit
            // even-aligned pairs directly (no scalar unpack, no repack).
            const ulonglong2* Bq = reinterpret_cast<const ulonglong2*>(
                Bb + ((ci * NROW + ty) * 2 + par) * SW + 4 * xi);
            uint64_t ep[12];
#pragma unroll
            for (int t = 0; t < 6; ++t) {
                const ulonglong2 v = Bq[t];
                ep[2 * t]     = v.x;
                ep[2 * t + 1] = v.y;
            }

            // kk=0: pair p -> ep[p]
            // kk=1: pair p -> ep[p+1]
            // kk=2: pair p -> ep[p+1]
            // kk=3: pair p -> ep[p+2]
#pragma unroll
            for (int p = 0; p < 10; ++p) {
                ffma2(accp[0][p], qp[0], ep[p]);
                ffma2(accp[1][p], qp[1], ep[p + 1]);
                ffma2(accp[2][p], qp[2], ep[p + 1]);
                ffma2(accp[3][p], qp[3], ep[p + 2]);
            }
            // scalar leftovers: kk even -> dxi=20 (j=20+kk); kk odd -> dxi=0 (j=kk)
            // wf[20]=lo(ep[10]), wf[22]=lo(ep[11]), wf[1]=hi(ep[0]), wf[3]=hi(ep[1])
            float lo10, hi10, lo11, hi11, lo0, hi0, lo1, hi1;
            upk2(ep[10], lo10, hi10);
            upk2(ep[11], lo11, hi11);
            upk2(ep[0],  lo0,  hi0);
            upk2(ep[1],  lo1,  hi1);
            accs[0] = fmaf(q4.x, lo10, accs[0]);
            accs[2] = fmaf(q4.z, lo11, accs[2]);
            accs[1] = fmaf(q4.y, hi0,  accs[1]);
            accs[3] = fmaf(q4.w, hi1,  accs[3]);
        }
    };

    // ---- software pipeline over 32 channel chunks, one sync per chunk ----
    loadRegs(0);
    stsRegs(0);
    __syncthreads();

    for (int k = 0; k < NCHK; ++k) {
        const int cur = k & 1;
        if (k + 1 < NCHK) {
            loadRegs(k + 1);
            stsRegs(1 - cur);
        }
        if (active) computeBuf(cur);
        __syncthreads();
    }

    // ---- write results ----
    if (active) {
        const float scale = 1.0f / 256.0f;
        const int obase = ((b * DD + dy_idx * GG) * HH + h) * WW + base_w;
#pragma unroll
        for (int kk = 0; kk < 4; ++kk) {
            const int dxi0 = (kk & 1) ? 1 : 0;        // first paired dxi
#pragma unroll
            for (int p = 0; p < 10; ++p) {
                float lo, hi;
                upk2(accp[kk][p], lo, hi);
                const int d0 = dxi0 + 2 * p;
                out[obase + d0 * (HH * WW) + 2 * kk]       = lo * scale;
                out[obase + (d0 + 1) * (HH * WW) + 2 * kk] = hi * scale;
            }
            const int ds = (kk & 1) ? 0 : 20;          // scalar leftover dxi
            out[obase + ds * (HH * WW) + 2 * kk] = accs[kk] * scale;
        }
    }
}

extern "C" void kernel_launch(void* const* d_in, const int* in_sizes, int n_in,
                              void* d_out, int out_size)
{
    const float* in1 = (const float*)d_in[0];
    const float* in2 = (const float*)d_in[1];
    float* out = (float*)d_out;

    (void)in_sizes; (void)n_in; (void)out_size;

    cudaFuncSetAttribute(corr_kernel,
                         cudaFuncAttributeMaxDynamicSharedMemorySize,
                         SMEM_BYTES);

    dim3 grid(2, HH, CB);
    dim3 block(32, NROW, 1);
    corr_kernel<<<grid, block, SMEM_BYTES>>>(in1, in2, out);
}